// round 7
// baseline (speedup 1.0000x reference)
#include <cuda_runtime.h>
#include <math.h>

#define SH_C0 0.28209479177387814f
#define SH_C1 0.4886025119029199f
#define NEAR_P 0.01f
#define FAR_P 1e10f
#define LOWPASS 0.3f
#define ALPHA_MIN (1.0f/255.0f)
#define ALPHA_MAX 0.999f

#define NMAX 1024
#define FULLMASK 0xffffffffu
#define TS 16
#define NT (TS*TS)
#define NW (NT/32)

// dynamic smem layout: sa[NMAX], sb[NMAX], sc[NMAX], keys[NMAX]
#define SMEM_BYTES (NMAX*(3*16 + 8))

__global__ __launch_bounds__(NT)
void fused_kernel(const float* __restrict__ means3d,
                  const float* __restrict__ quats,
                  const float* __restrict__ scales,
                  const float* __restrict__ opac,
                  const float* __restrict__ sh,
                  const float* __restrict__ c2w,
                  const float* __restrict__ Km,
                  float* __restrict__ out,
                  int N, int W, int H)
{
    extern __shared__ char smem[];
    float4* sa = (float4*)smem;                      // mx, my, conA, conB
    float4* sb = sa + NMAX;                          // conC, op, z, unused
    float4* sc = sb + NMAX;                          // r, g, b, unused
    unsigned long long* skey = (unsigned long long*)(sc + NMAX);
    __shared__ int s_wcnt[NW];

    int tid  = threadIdx.x;
    int lane = tid & 31;
    int warp = tid >> 5;

    // camera: viewmat = inverse of rigid camtoworld
    float R00=c2w[0], R01=c2w[1], R02=c2w[2],  t0=c2w[3];
    float R10=c2w[4], R11=c2w[5], R12=c2w[6],  t1=c2w[7];
    float R20=c2w[8], R21=c2w[9], R22=c2w[10], t2=c2w[11];
    float Rw00=R00, Rw01=R10, Rw02=R20;
    float Rw10=R01, Rw11=R11, Rw12=R21;
    float Rw20=R02, Rw21=R12, Rw22=R22;
    float tw0 = -(Rw00*t0 + Rw01*t1 + Rw02*t2);
    float tw1 = -(Rw10*t0 + Rw11*t1 + Rw12*t2);
    float tw2 = -(Rw20*t0 + Rw21*t1 + Rw22*t2);
    float fx=Km[0], cx=Km[2], fy=Km[4], cy=Km[5];

    // tile pixel-center bounds
    float tbx0 = blockIdx.x*TS + 0.5f, tbx1 = tbx0 + (TS-1);
    float tby0 = blockIdx.y*TS + 0.5f, tby1 = tby0 + (TS-1);

    // ---- phase 1: per-block preprocess + cull + compact ----
    int hbase = 0;
    for (int base = 0; base < N; base += NT) {
        int i = base + tid;
        bool hit = false;
        float4 pa, pb, pc;
        float zc = 0.f;
        if (i < N) {
            float m0 = means3d[3*i+0], m1 = means3d[3*i+1], m2 = means3d[3*i+2];
            float xc = Rw00*m0 + Rw01*m1 + Rw02*m2 + tw0;
            float yc = Rw10*m0 + Rw11*m1 + Rw12*m2 + tw1;
            zc       = Rw20*m0 + Rw21*m1 + Rw22*m2 + tw2;
            bool valid = (zc > NEAR_P) && (zc < FAR_P);
            float zs = valid ? zc : 1.0f;
            float iz = 1.0f / zs;
            float m2x = fx*xc*iz + cx;
            float m2y = fy*yc*iz + cy;

            float4 q4 = ((const float4*)quats)[i];
            float qw=q4.x, qx=q4.y, qy=q4.z, qz=q4.w;
            float qn = rsqrtf(qw*qw + qx*qx + qy*qy + qz*qz);
            qw*=qn; qx*=qn; qy*=qn; qz*=qn;
            float Rg[3][3];
            Rg[0][0]=1.f-2.f*(qy*qy+qz*qz); Rg[0][1]=2.f*(qx*qy-qw*qz); Rg[0][2]=2.f*(qx*qz+qw*qy);
            Rg[1][0]=2.f*(qx*qy+qw*qz); Rg[1][1]=1.f-2.f*(qx*qx+qz*qz); Rg[1][2]=2.f*(qy*qz-qw*qx);
            Rg[2][0]=2.f*(qx*qz-qw*qy); Rg[2][1]=2.f*(qy*qz+qw*qx); Rg[2][2]=1.f-2.f*(qx*qx+qy*qy);

            float s0=scales[3*i+0], s1=scales[3*i+1], s2=scales[3*i+2];
            float ss0=s0*s0, ss1=s1*s1, ss2=s2*s2;

            float C3[3][3];
            #pragma unroll
            for (int r=0;r<3;r++)
                #pragma unroll
                for (int c=0;c<3;c++)
                    C3[r][c] = Rg[r][0]*Rg[c][0]*ss0 + Rg[r][1]*Rg[c][1]*ss1 + Rg[r][2]*Rg[c][2]*ss2;

            float Rwm[3][3] = {{Rw00,Rw01,Rw02},{Rw10,Rw11,Rw12},{Rw20,Rw21,Rw22}};
            float T1[3][3], Cc[3][3];
            #pragma unroll
            for (int r=0;r<3;r++)
                #pragma unroll
                for (int c=0;c<3;c++)
                    T1[r][c] = Rwm[r][0]*C3[0][c] + Rwm[r][1]*C3[1][c] + Rwm[r][2]*C3[2][c];
            #pragma unroll
            for (int r=0;r<3;r++)
                #pragma unroll
                for (int c=0;c<3;c++)
                    Cc[r][c] = T1[r][0]*Rwm[c][0] + T1[r][1]*Rwm[c][1] + T1[r][2]*Rwm[c][2];

            float J00 = fx*iz,  J02 = -fx*xc*iz*iz;
            float J11 = fy*iz,  J12 = -fy*yc*iz*iz;
            float v00 = J00*Cc[0][0] + J02*Cc[2][0];
            float v01 = J00*Cc[0][1] + J02*Cc[2][1];
            float v02 = J00*Cc[0][2] + J02*Cc[2][2];
            float v11 = J11*Cc[1][1] + J12*Cc[2][1];
            float v12 = J11*Cc[1][2] + J12*Cc[2][2];
            float c00 = v00*J00 + v02*J02;
            float c01 = v01*J11 + v02*J12;
            float c11 = v11*J11 + v12*J12;

            float A = c00 + LOWPASS;
            float B = c01;
            float Cq = c11 + LOWPASS;
            float det = A*Cq - B*B;
            valid = valid && (det > 0.f);
            float dets = (det > 0.f) ? det : 1.f;
            float idet = 1.f / dets;
            float conA = Cq*idet, conB = -B*idet, conC = A*idet;

            float opa = 1.f / (1.f + __expf(-opac[i]));
            float op = valid ? opa : 0.f;

            // exact footprint bbox: alpha >= 1/255 <=> sigma <= tau = ln(255*op)
            float t255 = op * 255.f;
            if (valid && t255 > 1.f) {
                float tau = logf(t255);
                float rx = sqrtf(2.f * tau * A);
                float ry = sqrtf(2.f * tau * Cq);
                hit = (m2x + rx >= tbx0) && (m2x - rx <= tbx1)
                   && (m2y + ry >= tby0) && (m2y - ry <= tby1);
            }

            if (hit) {
                float dx = m0 - t0, dy = m1 - t1, dz = m2 - t2;
                float dn = sqrtf(dx*dx + dy*dy + dz*dz);
                float inv = 1.f / fmaxf(dn, 1e-8f);
                dx*=inv; dy*=inv; dz*=inv;
                const float* shp = sh + 12*i;
                float colr = SH_C0*shp[0] - SH_C1*dy*shp[3] + SH_C1*dz*shp[6] - SH_C1*dx*shp[9];
                float colg = SH_C0*shp[1] - SH_C1*dy*shp[4] + SH_C1*dz*shp[7] - SH_C1*dx*shp[10];
                float colb = SH_C0*shp[2] - SH_C1*dy*shp[5] + SH_C1*dz*shp[8] - SH_C1*dx*shp[11];
                colr = fmaxf(colr + 0.5f, 0.f);
                colg = fmaxf(colg + 0.5f, 0.f);
                colb = fmaxf(colb + 0.5f, 0.f);
                pa = make_float4(m2x, m2y, conA, conB);
                pb = make_float4(conC, op, zc, 0.f);
                pc = make_float4(colr, colg, colb, 0.f);
            }
        }

        unsigned bm = __ballot_sync(FULLMASK, hit);
        if (lane == 0) s_wcnt[warp] = __popc(bm);
        __syncthreads();
        int off = hbase, chunktotal = 0;
        #pragma unroll
        for (int w2 = 0; w2 < NW; w2++) {
            int v = s_wcnt[w2];
            chunktotal += v;
            if (w2 < warp) off += v;
        }
        off += __popc(bm & ((1u << lane) - 1u));
        if (hit) {
            sa[off] = pa; sb[off] = pb; sc[off] = pc;
            // key: depth bits (positive float -> monotonic uint), tie-break by slot
            skey[off] = ((unsigned long long)__float_as_uint(zc) << 32) | (unsigned)off;
        }
        hbase += chunktotal;
        __syncthreads();   // protect s_wcnt reuse
    }
    int total = hbase;

    // ---- phase 2: bitonic sort keys[0..total) ascending (pad to pow2) ----
    if (total > 1) {
        int M = 1;
        while (M < total) M <<= 1;
        for (int k = total + tid; k < M; k += NT)
            skey[k] = 0xFFFFFFFFFFFFFFFFull;
        __syncthreads();
        for (int len = 2; len <= M; len <<= 1) {
            for (int stride = len >> 1; stride > 0; stride >>= 1) {
                for (int t = tid; t < (M >> 1); t += NT) {
                    int i = 2*stride*(t/stride) + (t%stride);
                    int j = i + stride;
                    bool asc = ((i & len) == 0);
                    unsigned long long a = skey[i], b = skey[j];
                    if ((a > b) == asc) { skey[i] = b; skey[j] = a; }
                }
                __syncthreads();
            }
        }
    } else {
        __syncthreads();
    }

    // ---- phase 3: per-pixel front-to-back composite in sorted order ----
    int tx = tid & (TS-1);
    int ty = tid >> 4;
    int x = blockIdx.x*TS + tx;
    int y = blockIdx.y*TS + ty;
    float pxf = x + 0.5f, pyf = y + 0.5f;

    float Tt = 1.f, cr = 0.f, cg = 0.f, cb = 0.f, acc = 0.f, ed = 0.f;
    for (int k = 0; k < total; k++) {
        int slot = (int)(unsigned)skey[k];
        float4 a  = sa[slot];
        float ddx = pxf - a.x;
        float ddy = pyf - a.y;
        float4 bq = sb[slot];
        float sigma = 0.5f*(a.z*ddx*ddx + bq.x*ddy*ddy) + a.w*ddx*ddy;
        float alpha = fminf(bq.y * __expf(-sigma), ALPHA_MAX);
        if (sigma >= 0.f && alpha >= ALPHA_MIN) {
            float w = alpha * Tt;
            float4 cq = sc[slot];
            cr += w*cq.x; cg += w*cq.y; cb += w*cq.z;
            acc += w; ed += w*bq.z;
            Tt *= (1.f - alpha);
            if (Tt < 1e-5f) break;
        }
    }

    if (x < W && y < H) {
        int pid = y*W + x;
        float edv = ed / fmaxf(acc, 1e-10f);
        ((float4*)out)[pid] = make_float4(cr, cg, cb, edv);
        out[W*H*4 + pid] = acc;
    }
}

extern "C" void kernel_launch(void* const* d_in, const int* in_sizes, int n_in,
                              void* d_out, int out_size) {
    const float* means3d = (const float*)d_in[0];
    const float* quats   = (const float*)d_in[1];
    const float* scales  = (const float*)d_in[2];
    const float* opac    = (const float*)d_in[3];
    const float* sh      = (const float*)d_in[4];
    const float* c2w     = (const float*)d_in[5];
    const float* Km      = (const float*)d_in[6];
    int N = in_sizes[0] / 3;
    if (N > NMAX) N = NMAX;

    int P = out_size / 5;
    int W = (int)(sqrtf((float)P) + 0.5f);
    int H = W;

    static bool attr_set = false;
    if (!attr_set) {
        cudaFuncSetAttribute(fused_kernel,
                             cudaFuncAttributeMaxDynamicSharedMemorySize, SMEM_BYTES);
        attr_set = true;
    }

    dim3 grid((W + TS - 1)/TS, (H + TS - 1)/TS);
    fused_kernel<<<grid, NT, SMEM_BYTES>>>(means3d, quats, scales, opac, sh,
                                           c2w, Km, (float*)d_out, N, W, H);
}